// round 15
// baseline (speedup 1.0000x reference)
#include <cuda_runtime.h>
#include <cuda_fp16.h>
#include <cstdint>
#include <math.h>

// ---------------- constants ----------------
#define Dd      16
#define CTXd    128
#define SAMP    64            // 2 groups x 32 samples
#define THREADS 512
#define STRB    400           // act row pitch (bytes)
#define BUFB    25600         // one act buffer: 64 rows x 400B
#define GRPB    (2*BUFB)      // ping-pong pair per group
#define SM_TOT  (2*GRPB)      // 102400

// fragment-image block counts (one block = n16 x k16 = 128 uint32 = 512B)
#define W1BLK   (12*9)
#define W2BLK   (12*12)
#define W3BLK   12

__device__ __align__(16) uint32_t g_w1f[W1BLK*128];
__device__ __align__(16) uint32_t g_w2f[W2BLK*128];
__device__ __align__(16) uint32_t g_w3f[W3BLK*128];
__device__ float g_b1p[192];

// ---------------- prep: weights -> mma-B fragment order ----------------
__global__ void prep(const float* __restrict__ W1, const float* __restrict__ W2,
                     const float* __restrict__ W3, const float* __restrict__ b1,
                     const float* __restrict__ t)
{
    int idx = blockIdx.x * blockDim.x + threadIdx.x;
    const float* W; uint32_t* img; int ktn, N, i;
    if (idx < W1BLK*128)               { i = idx;              W = W1; img = g_w1f; ktn = 9;  N = 192; }
    else if (idx < (W1BLK+W2BLK)*128)  { i = idx - W1BLK*128;  W = W2; img = g_w2f; ktn = 12; N = 192; }
    else if (idx < (W1BLK+W2BLK+W3BLK)*128)
                                       { i = idx - (W1BLK+W2BLK)*128; W = W3; img = g_w3f; ktn = 12; N = 16; }
    else if (idx < (W1BLK+W2BLK+W3BLK)*128 + 192) {
        int n = idx - (W1BLK+W2BLK+W3BLK)*128;
        g_b1p[n] = b1[n] + t[0] * W1[144 * 192 + n];
        return;
    } else return;

    int blk = i >> 7, li = i & 127;
    int lane = li >> 2, r = li & 3;
    int n16g = blk / ktn, kt = blk - n16g * ktn;
    int n = n16g * 16 + (lane >> 2) + ((r >> 1) & 1) * 8;
    int k = kt * 16 + 2 * (lane & 3) + (r & 1) * 8;
    __half2 v = __floats2half2_rn(W[(size_t)k * N + n], W[(size_t)(k + 1) * N + n]);
    img[i] = *(uint32_t*)&v;
}

// ---------------- PTX helpers ----------------
__device__ __forceinline__ uint32_t smem_u32(const void* p) {
    uint32_t a;
    asm("{ .reg .u64 t; cvta.to.shared.u64 t, %1; cvt.u32.u64 %0, t; }" : "=r"(a) : "l"(p));
    return a;
}
__device__ __forceinline__ void barg(int id) {
    asm volatile("bar.sync %0, %1;" :: "r"(id), "r"(256) : "memory");
}
__device__ __forceinline__ void ldsm4(uint32_t (&r)[4], uint32_t addr) {
    asm volatile("ldmatrix.sync.aligned.m8n8.x4.shared.b16 {%0,%1,%2,%3}, [%4];"
                 : "=r"(r[0]), "=r"(r[1]), "=r"(r[2]), "=r"(r[3]) : "r"(addr));
}
__device__ __forceinline__ void mma16816(float (&d)[4], const uint32_t (&a)[4],
                                         uint32_t b0, uint32_t b1)
{
    asm volatile("mma.sync.aligned.m16n8k16.row.col.f32.f16.f16.f32 "
                 "{%0,%1,%2,%3}, {%4,%5,%6,%7}, {%8,%9}, {%0,%1,%2,%3};"
                 : "+f"(d[0]), "+f"(d[1]), "+f"(d[2]), "+f"(d[3])
                 : "r"(a[0]), "r"(a[1]), "r"(a[2]), "r"(a[3]), "r"(b0), "r"(b1));
}
__device__ __forceinline__ void ldgB(uint32_t (&b)[4], const uint32_t* __restrict__ img,
                                     int blk, int lane)
{
    const uint4 v = __ldg((const uint4*)(img + blk * 128 + lane * 4));
    b[0] = v.x; b[1] = v.y; b[2] = v.z; b[3] = v.w;
}
__device__ __forceinline__ uint32_t aAddr(uint32_t base, int m0, int kt, int lane) {
    int row = m0 + (lane & 7) + ((lane >> 3) & 1) * 8;
    return base + row * STRB + kt * 32 + ((lane >> 4) & 1) * 16;
}
__device__ __forceinline__ void stH2(char* sm, int row, int c0, float v0, float v1) {
    *(__half2*)(sm + row * STRB + c0 * 2) = __floats2half2_rn(v0, v1);
}
__device__ __forceinline__ uint32_t packh2(float v0, float v1) {
    __half2 hh = __floats2half2_rn(v0, v1);
    return *(uint32_t*)&hh;
}
__device__ __forceinline__ float rcpa(float x) {
    float r; asm("rcp.approx.f32 %0, %1;" : "=f"(r) : "f"(x)); return r;
}

// Fast exact-GELU + derivative via A&S 7.1.26, reusing E=exp(-a^2/2).
#define GA1  0.127414796f
#define GA2 -0.142248368f
#define GA3  0.71070687f
#define GA4 -0.72657601f
#define GA5  0.53070271f
__device__ __forceinline__ void gelu2(float a0, float a1, float& g0, float& g1,
                                      float& p0, float& p1)
{
    float e0 = __expf(-0.5f * a0 * a0);
    float e1 = __expf(-0.5f * a1 * a1);
    float x0 = fabsf(a0) * 0.70710678f;
    float x1 = fabsf(a1) * 0.70710678f;
    float t0 = rcpa(fmaf(0.3275911f, x0, 1.0f));
    float t1 = rcpa(fmaf(0.3275911f, x1, 1.0f));
    float s0 = t0 * fmaf(t0, fmaf(t0, fmaf(t0, fmaf(t0, GA5, GA4), GA3), GA2), GA1);
    float s1 = t1 * fmaf(t1, fmaf(t1, fmaf(t1, fmaf(t1, GA5, GA4), GA3), GA2), GA1);
    float q0 = s0 * e0;
    float q1 = s1 * e1;
    float c0 = (a0 >= 0.f) ? (1.0f - q0) : q0;
    float c1 = (a1 >= 0.f) ? (1.0f - q1) : q1;
    g0 = a0 * c0;  g1 = a1 * c1;
    p0 = fmaf(a0, 0.3989423f * e0, c0);
    p1 = fmaf(a1, 0.3989423f * e1, c1);
}

// layer-1 epilogue: bias + gelu on primal frag, gelu'(a)*u on tangent -> smem
__device__ __forceinline__ void epilogue(float (&accP)[6][4], float (&accT)[6][4],
                                         const float* __restrict__ bias, char* sDst,
                                         int mh, int n0, int lane)
{
    const int r0 = mh * 16 + (lane >> 2);
    const int cl = 2 * (lane & 3);
#pragma unroll
    for (int nt = 0; nt < 6; nt++) {
        const int c0 = n0 + 8 * nt + cl;
        const float2 bb = __ldg((const float2*)(bias + c0));
#pragma unroll
        for (int rh = 0; rh < 2; rh++) {
            const int s = r0 + 8 * rh;
            float a0 = accP[nt][2 * rh]     + bb.x;
            float a1 = accP[nt][2 * rh + 1] + bb.y;
            float g0, g1, p0, p1;
            gelu2(a0, a1, g0, g1, p0, p1);
            stH2(sDst, s, c0, g0, g1);
            stH2(sDst, 32 + s, c0, accT[nt][2 * rh] * p0, accT[nt][2 * rh + 1] * p1);
        }
    }
}

// stage one tile's primal inputs [y | h] into buf0 rows 0..31
__device__ __forceinline__ void stage_inputs(char* sAct0, const float* __restrict__ y,
                                             const float* __restrict__ h,
                                             int srow, int gtid)
{
    const int s = gtid >> 3, kb = gtid & 7;
    {
        const int k = 2 * kb;
        float2 v = *(const float2*)(y + (size_t)(srow + s) * Dd + k);
        stH2(sAct0, s, k, v.x, v.y);
    }
#pragma unroll
    for (int j = 1; j < 9; j++) {
        const int k = 2 * (kb + 8 * j);
        float2 v = *(const float2*)(h + (size_t)(srow + s) * CTXd + (k - 16));
        stH2(sAct0, s, k, v.x, v.y);
    }
}

// ---------------- main kernel (persistent) ----------------
__global__ void __launch_bounds__(THREADS, 1)
odefunc_mma13(const float* __restrict__ y,
              const float* __restrict__ h,
              const float* __restrict__ eps,
              const float* __restrict__ b2,
              const float* __restrict__ b3,
              float* __restrict__ out, int Bsz, int ntiles)
{
    extern __shared__ __align__(16) char smem[];

    const int tid  = threadIdx.x;
    const int lane = tid & 31;
    const int w    = tid >> 5;          // 0..15
    const int g    = w >> 3;            // sample group 0/1
    const int wg   = w & 7;             // warp within group
    const int nq   = wg & 3;            // n-quarter (48 cols)
    const int mh   = wg >> 2;           // m-half (16 rows) 0/1
    const int n0   = nq * 48;
    const int gtid = tid & 255;
    const int bid  = g + 1;             // named barrier id

    char* sAct0 = smem + g * GRPB;          // ping
    char* sAct1 = sAct0 + BUFB;             // pong
    const uint32_t swA0 = smem_u32(sAct0);
    const uint32_t swA1 = swA0 + BUFB;
    float* sRed = (float*)sAct1;            // partials alias pong after bar3

    float* outF    = out;
    float* outLogp = out + (size_t)Bsz * Dd;
    float* outDh   = out + (size_t)Bsz * (Dd + 1);
    const float b3c = __ldg(b3 + (gtid & 15));   // loop-invariant

    int tile = blockIdx.x;
    if (tile >= ntiles) return;
    stage_inputs(sAct0, y, h, tile * SAMP + g * 32, gtid);

    for (; tile < ntiles; tile += gridDim.x) {
        const int srow0 = tile * SAMP + g * 32;
        barg(bid);                        // bar1: buf0 inputs ready

        // ---------------- layer 1 (reads buf0) ----------------
        float accP[6][4], accT[6][4];
#pragma unroll
        for (int j = 0; j < 6; j++)
#pragma unroll
            for (int q = 0; q < 4; q++) accP[j][q] = 0.f;

        uint32_t aT[4];
        {
            const float* eb = eps + (size_t)(srow0 + mh * 16) * Dd;
            const int rr = lane >> 2, cc = 2 * (lane & 3);
            aT[0] = packh2(eb[rr * Dd + cc],       eb[rr * Dd + cc + 1]);
            aT[1] = packh2(eb[(rr + 8) * Dd + cc], eb[(rr + 8) * Dd + cc + 1]);
            aT[2] = packh2(eb[rr * Dd + cc + 8],   eb[rr * Dd + cc + 9]);
            aT[3] = packh2(eb[(rr + 8) * Dd + cc + 8], eb[(rr + 8) * Dd + cc + 9]);
        }

        {   // primal mainloop with B double-buffer
            uint32_t bA[3][4], bB[3][4];
#pragma unroll
            for (int np = 0; np < 3; np++)
                ldgB(bA[np], g_w1f, (nq * 3 + np) * 9 + 0, lane);
#pragma unroll
            for (int kt = 0; kt < 9; kt++) {
                uint32_t (&bc)[3][4] = (kt & 1) ? bB : bA;
                uint32_t (&bn)[3][4] = (kt & 1) ? bA : bB;
                if (kt < 8) {
#pragma unroll
                    for (int np = 0; np < 3; np++)
                        ldgB(bn[np], g_w1f, (nq * 3 + np) * 9 + kt + 1, lane);
                }
                uint32_t aP[4];
                ldsm4(aP, aAddr(swA0, mh * 16, kt, lane));
#pragma unroll
                for (int np = 0; np < 3; np++) {
                    mma16816(accP[2 * np],     aP, bc[np][0], bc[np][1]);
                    mma16816(accP[2 * np + 1], aP, bc[np][2], bc[np][3]);
                }
            }
        }
        // tangent pass: kt0 only
#pragma unroll
        for (int j = 0; j < 6; j++)
#pragma unroll
            for (int q = 0; q < 4; q++) accT[j][q] = 0.f;
#pragma unroll
        for (int np = 0; np < 3; np++) {
            uint32_t b[4];
            ldgB(b, g_w1f, (nq * 3 + np) * 9 + 0, lane);
            mma16816(accT[2 * np],     aT, b[0], b[1]);
            mma16816(accT[2 * np + 1], aT, b[2], b[3]);
        }

        epilogue(accP, accT, g_b1p, sAct1, mh, n0, lane);
        barg(bid);                        // bar2: buf1 acts ready; buf0 free

        // ---- prefetch next tile's inputs into buf0 (hides under layer 2) ----
        const int nx = tile + gridDim.x;
        if (nx < ntiles) stage_inputs(sAct0, y, h, nx * SAMP + g * 32, gtid);

        // ---------------- layer 2 (reads buf1) ----------------
#pragma unroll
        for (int j = 0; j < 6; j++)
#pragma unroll
            for (int q = 0; q < 4; q++) { accP[j][q] = 0.f; accT[j][q] = 0.f; }
        {
            uint32_t bA[3][4], bB[3][4];
#pragma unroll
            for (int np = 0; np < 3; np++)
                ldgB(bA[np], g_w2f, (nq * 3 + np) * 12 + 0, lane);
#pragma unroll
            for (int kt = 0; kt < 12; kt++) {
                uint32_t (&bc)[3][4] = (kt & 1) ? bB : bA;
                uint32_t (&bn)[3][4] = (kt & 1) ? bA : bB;
                if (kt < 11) {
#pragma unroll
                    for (int np = 0; np < 3; np++)
                        ldgB(bn[np], g_w2f, (nq * 3 + np) * 12 + kt + 1, lane);
                }
                uint32_t aP[4], aTk[4];
                ldsm4(aP,  aAddr(swA1, mh * 16,      kt, lane));
                ldsm4(aTk, aAddr(swA1, 32 + mh * 16, kt, lane));
#pragma unroll
                for (int np = 0; np < 3; np++) {
                    mma16816(accP[2 * np],     aP,  bc[np][0], bc[np][1]);
                    mma16816(accP[2 * np + 1], aP,  bc[np][2], bc[np][3]);
                    mma16816(accT[2 * np],     aTk, bc[np][0], bc[np][1]);
                    mma16816(accT[2 * np + 1], aTk, bc[np][2], bc[np][3]);
                }
            }
        }

        // ---- fused epilogue-2 + layer 3, all in registers ----
        // warp nq covers k-steps nq*3 .. nq*3+2 of layer 3 (its own 48 cols)
        float acc3P[2][4], acc3T[2][4];
#pragma unroll
        for (int j = 0; j < 2; j++)
#pragma unroll
            for (int q = 0; q < 4; q++) { acc3P[j][q] = 0.f; acc3T[j][q] = 0.f; }
        {
            const int cl = 2 * (lane & 3);
#pragma unroll
            for (int ktp = 0; ktp < 3; ktp++) {
                uint32_t aZ[4], aU[4];
#pragma unroll
                for (int hf = 0; hf < 2; hf++) {
                    const int nt = 2 * ktp + hf;
                    const float2 bb = __ldg((const float2*)(b2 + n0 + 8 * nt + cl));
                    float a0 = accP[nt][0] + bb.x, a1 = accP[nt][1] + bb.y;
                    float a2 = accP[nt][2] + bb.x, a3 = accP[nt][3] + bb.y;
                    float g0, g1, p0, p1, g2, g3, p2, p3;
                    gelu2(a0, a1, g0, g1, p0, p1);
                    gelu2(a2, a3, g2, g3, p2, p3);
                    aZ[2 * hf]     = packh2(g0, g1);
                    aZ[2 * hf + 1] = packh2(g2, g3);
                    aU[2 * hf]     = packh2(accT[nt][0] * p0, accT[nt][1] * p1);
                    aU[2 * hf + 1] = packh2(accT[nt][2] * p2, accT[nt][3] * p3);
                }
                uint32_t b[4];
                ldgB(b, g_w3f, nq * 3 + ktp, lane);
                mma16816(acc3P[0], aZ, b[0], b[1]);
                mma16816(acc3P[1], aZ, b[2], b[3]);
                mma16816(acc3T[0], aU, b[0], b[1]);
                mma16816(acc3T[1], aU, b[2], b[3]);
            }
        }
        barg(bid);                        // bar3: all buf1 L2 reads done

        {   // partials -> sRed (buf1): [nq][64 rows][16]
            float* red = sRed + nq * 1024;
            const int rbase = mh * 16 + (lane >> 2);
            const int cl = 2 * (lane & 3);
#pragma unroll
            for (int nt = 0; nt < 2; nt++)
#pragma unroll
                for (int rh = 0; rh < 2; rh++) {
                    const int r = rbase + 8 * rh;
                    const int c = 8 * nt + cl;
                    *(float2*)(red + r * 16 + c) =
                        make_float2(acc3P[nt][2 * rh], acc3P[nt][2 * rh + 1]);
                    *(float2*)(red + (32 + r) * 16 + c) =
                        make_float2(acc3T[nt][2 * rh], acc3T[nt][2 * rh + 1]);
                }
        }
        barg(bid);                        // bar4: partials ready

        // ---------------- outputs for this tile ----------------
        {   // zero dh
            float4* dhp = (float4*)(outDh + (size_t)srow0 * CTXd);
            const float4 z4 = make_float4(0.f, 0.f, 0.f, 0.f);
            for (int i = gtid; i < 32 * CTXd / 4; i += 256) dhp[i] = z4;
        }
        for (int i = gtid; i < 32 * 16; i += 256) {
            const int s = i >> 4, c = i & 15;
            float v = sRed[s * 16 + c] + sRed[1024 + s * 16 + c]
                    + sRed[2048 + s * 16 + c] + sRed[3072 + s * 16 + c];
            outF[(size_t)(srow0 + s) * Dd + c] = v + b3c;
        }
        {
            const int s = gtid >> 3, g8 = gtid & 7, c0 = 2 * g8;
            const float* rt_ = sRed + 512 + s * 16 + c0;
            float j0 = rt_[0] + rt_[1024] + rt_[2048] + rt_[3072];
            float j1 = rt_[1] + rt_[1025] + rt_[2049] + rt_[3073];
            float2 ev = *(const float2*)(eps + (size_t)(srow0 + s) * Dd + c0);
            float dot = j0 * ev.x + j1 * ev.y;
            dot += __shfl_xor_sync(0xffffffffu, dot, 1);
            dot += __shfl_xor_sync(0xffffffffu, dot, 2);
            dot += __shfl_xor_sync(0xffffffffu, dot, 4);
            if (g8 == 0) outLogp[srow0 + s] = -dot;
        }
    }
}

// ---------------- launcher ----------------
extern "C" void kernel_launch(void* const* d_in, const int* in_sizes, int n_in,
                              void* d_out, int out_size)
{
    const float* t   = (const float*)d_in[0];
    const float* y   = (const float*)d_in[1];
    const float* h   = (const float*)d_in[3];
    const float* eps = (const float*)d_in[4];
    const float* W1  = (const float*)d_in[5];
    const float* b1  = (const float*)d_in[6];
    const float* W2  = (const float*)d_in[7];
    const float* b2  = (const float*)d_in[8];
    const float* W3  = (const float*)d_in[9];
    const float* b3  = (const float*)d_in[10];

    const int Bsz = in_sizes[1] / Dd;
    const int ntiles = Bsz / SAMP;

    const int prepN = (W1BLK + W2BLK + W3BLK) * 128 + 192;
    prep<<<(prepN + 255) / 256, 256>>>(W1, W2, W3, b1, t);

    int smCount = 0;
    cudaDeviceGetAttribute(&smCount, cudaDevAttrMultiProcessorCount, 0);
    if (smCount <= 0) smCount = 148;
    int grid = smCount < ntiles ? smCount : ntiles;

    cudaFuncSetAttribute(odefunc_mma13,
                         cudaFuncAttributeMaxDynamicSharedMemorySize, SM_TOT);
    odefunc_mma13<<<grid, THREADS, SM_TOT>>>(
        y, h, eps, b2, b3, (float*)d_out, Bsz, ntiles);
}

// round 16
// speedup vs baseline: 1.0575x; 1.0575x over previous
#include <cuda_runtime.h>
#include <cuda_fp16.h>
#include <cstdint>
#include <math.h>

// ---------------- constants ----------------
#define Dd      16
#define CTXd    128
#define SAMP    32            // one CTA = one 32-sample group
#define THREADS 256
#define STRB    400           // act row pitch (bytes)
#define BUFB    25600         // one act buffer: 64 rows x 400B
#define SM_TOT  (2*BUFB)      // 51200 per CTA (ping-pong)

// fragment-image block counts (one block = n16 x k16 = 128 uint32 = 512B)
#define W1BLK   (12*9)
#define W2BLK   (12*12)
#define W3BLK   12

__device__ __align__(16) uint32_t g_w1f[W1BLK*128];
__device__ __align__(16) uint32_t g_w2f[W2BLK*128];
__device__ __align__(16) uint32_t g_w3f[W3BLK*128];
__device__ float g_b1p[192];

// ---------------- prep: weights -> mma-B fragment order ----------------
__global__ void prep(const float* __restrict__ W1, const float* __restrict__ W2,
                     const float* __restrict__ W3, const float* __restrict__ b1,
                     const float* __restrict__ t)
{
    int idx = blockIdx.x * blockDim.x + threadIdx.x;
    const float* W; uint32_t* img; int ktn, N, i;
    if (idx < W1BLK*128)               { i = idx;              W = W1; img = g_w1f; ktn = 9;  N = 192; }
    else if (idx < (W1BLK+W2BLK)*128)  { i = idx - W1BLK*128;  W = W2; img = g_w2f; ktn = 12; N = 192; }
    else if (idx < (W1BLK+W2BLK+W3BLK)*128)
                                       { i = idx - (W1BLK+W2BLK)*128; W = W3; img = g_w3f; ktn = 12; N = 16; }
    else if (idx < (W1BLK+W2BLK+W3BLK)*128 + 192) {
        int n = idx - (W1BLK+W2BLK+W3BLK)*128;
        g_b1p[n] = b1[n] + t[0] * W1[144 * 192 + n];
        return;
    } else return;

    int blk = i >> 7, li = i & 127;
    int lane = li >> 2, r = li & 3;
    int n16g = blk / ktn, kt = blk - n16g * ktn;
    int n = n16g * 16 + (lane >> 2) + ((r >> 1) & 1) * 8;
    int k = kt * 16 + 2 * (lane & 3) + (r & 1) * 8;
    __half2 v = __floats2half2_rn(W[(size_t)k * N + n], W[(size_t)(k + 1) * N + n]);
    img[i] = *(uint32_t*)&v;
}

// ---------------- PTX helpers ----------------
__device__ __forceinline__ uint32_t smem_u32(const void* p) {
    uint32_t a;
    asm("{ .reg .u64 t; cvta.to.shared.u64 t, %1; cvt.u32.u64 %0, t; }" : "=r"(a) : "l"(p));
    return a;
}
__device__ __forceinline__ void ldsm4(uint32_t (&r)[4], uint32_t addr) {
    asm volatile("ldmatrix.sync.aligned.m8n8.x4.shared.b16 {%0,%1,%2,%3}, [%4];"
                 : "=r"(r[0]), "=r"(r[1]), "=r"(r[2]), "=r"(r[3]) : "r"(addr));
}
__device__ __forceinline__ void mma16816(float (&d)[4], const uint32_t (&a)[4],
                                         uint32_t b0, uint32_t b1)
{
    asm volatile("mma.sync.aligned.m16n8k16.row.col.f32.f16.f16.f32 "
                 "{%0,%1,%2,%3}, {%4,%5,%6,%7}, {%8,%9}, {%0,%1,%2,%3};"
                 : "+f"(d[0]), "+f"(d[1]), "+f"(d[2]), "+f"(d[3])
                 : "r"(a[0]), "r"(a[1]), "r"(a[2]), "r"(a[3]), "r"(b0), "r"(b1));
}
__device__ __forceinline__ void ldgB(uint32_t (&b)[4], const uint32_t* __restrict__ img,
                                     int blk, int lane)
{
    const uint4 v = __ldg((const uint4*)(img + blk * 128 + lane * 4));
    b[0] = v.x; b[1] = v.y; b[2] = v.z; b[3] = v.w;
}
__device__ __forceinline__ uint32_t aAddr(uint32_t base, int m0, int kt, int lane) {
    int row = m0 + (lane & 7) + ((lane >> 3) & 1) * 8;
    return base + row * STRB + kt * 32 + ((lane >> 4) & 1) * 16;
}
__device__ __forceinline__ void stH2(char* sm, int row, int c0, float v0, float v1) {
    *(__half2*)(sm + row * STRB + c0 * 2) = __floats2half2_rn(v0, v1);
}
__device__ __forceinline__ uint32_t packh2(float v0, float v1) {
    __half2 hh = __floats2half2_rn(v0, v1);
    return *(uint32_t*)&hh;
}
__device__ __forceinline__ float rcpa(float x) {
    float r; asm("rcp.approx.f32 %0, %1;" : "=f"(r) : "f"(x)); return r;
}

// Fast exact-GELU + derivative via A&S 7.1.26, reusing E=exp(-a^2/2).
#define GA1  0.127414796f
#define GA2 -0.142248368f
#define GA3  0.71070687f
#define GA4 -0.72657601f
#define GA5  0.53070271f
__device__ __forceinline__ void gelu2(float a0, float a1, float& g0, float& g1,
                                      float& p0, float& p1)
{
    float e0 = __expf(-0.5f * a0 * a0);
    float e1 = __expf(-0.5f * a1 * a1);
    float x0 = fabsf(a0) * 0.70710678f;
    float x1 = fabsf(a1) * 0.70710678f;
    float t0 = rcpa(fmaf(0.3275911f, x0, 1.0f));
    float t1 = rcpa(fmaf(0.3275911f, x1, 1.0f));
    float s0 = t0 * fmaf(t0, fmaf(t0, fmaf(t0, fmaf(t0, GA5, GA4), GA3), GA2), GA1);
    float s1 = t1 * fmaf(t1, fmaf(t1, fmaf(t1, fmaf(t1, GA5, GA4), GA3), GA2), GA1);
    float q0 = s0 * e0;
    float q1 = s1 * e1;
    float c0 = (a0 >= 0.f) ? (1.0f - q0) : q0;
    float c1 = (a1 >= 0.f) ? (1.0f - q1) : q1;
    g0 = a0 * c0;  g1 = a1 * c1;
    p0 = fmaf(a0, 0.3989423f * e0, c0);
    p1 = fmaf(a1, 0.3989423f * e1, c1);
}

// bias + gelu on primal frag, gelu'(a)*u on tangent frag -> dst act buffer
__device__ __forceinline__ void epilogue(float (&accP)[6][4], float (&accT)[6][4],
                                         const float* __restrict__ bias, char* sDst,
                                         int mh, int n0, int lane)
{
    const int r0 = mh * 16 + (lane >> 2);
    const int cl = 2 * (lane & 3);
#pragma unroll
    for (int nt = 0; nt < 6; nt++) {
        const int c0 = n0 + 8 * nt + cl;
        const float2 bb = __ldg((const float2*)(bias + c0));
#pragma unroll
        for (int rh = 0; rh < 2; rh++) {
            const int s = r0 + 8 * rh;
            float a0 = accP[nt][2 * rh]     + bb.x;
            float a1 = accP[nt][2 * rh + 1] + bb.y;
            float g0, g1, p0, p1;
            gelu2(a0, a1, g0, g1, p0, p1);
            stH2(sDst, s, c0, g0, g1);
            stH2(sDst, 32 + s, c0, accT[nt][2 * rh] * p0, accT[nt][2 * rh + 1] * p1);
        }
    }
}

// stage one tile's primal inputs [y | h] into buf0 rows 0..31
__device__ __forceinline__ void stage_inputs(char* sAct0, const float* __restrict__ y,
                                             const float* __restrict__ h,
                                             int srow, int tid)
{
    const int s = tid >> 3, kb = tid & 7;
    {
        const int k = 2 * kb;
        float2 v = *(const float2*)(y + (size_t)(srow + s) * Dd + k);
        stH2(sAct0, s, k, v.x, v.y);
    }
#pragma unroll
    for (int j = 1; j < 9; j++) {
        const int k = 2 * (kb + 8 * j);
        float2 v = *(const float2*)(h + (size_t)(srow + s) * CTXd + (k - 16));
        stH2(sAct0, s, k, v.x, v.y);
    }
}

// ---------------- main kernel (persistent, 3 CTAs/SM) ----------------
__global__ void __launch_bounds__(THREADS, 3)
odefunc_mma14(const float* __restrict__ y,
              const float* __restrict__ h,
              const float* __restrict__ eps,
              const float* __restrict__ b2,
              const float* __restrict__ b3,
              float* __restrict__ out, int Bsz, int ntiles)
{
    extern __shared__ __align__(16) char smem[];

    const int tid  = threadIdx.x;
    const int lane = tid & 31;
    const int w    = tid >> 5;          // 0..7
    const int nq   = w & 3;             // n-quarter (48 cols)
    const int mh   = w >> 2;            // m-half (16 rows) 0/1
    const int n0   = nq * 48;

    char* sAct0 = smem;                 // ping
    char* sAct1 = smem + BUFB;          // pong
    const uint32_t swA0 = smem_u32(sAct0);
    const uint32_t swA1 = swA0 + BUFB;
    float* sRed = (float*)sAct1;        // partials alias pong after bar3

    float* outF    = out;
    float* outLogp = out + (size_t)Bsz * Dd;
    float* outDh   = out + (size_t)Bsz * (Dd + 1);
    const float b3c = __ldg(b3 + (tid & 15));   // loop-invariant

    int tile = blockIdx.x;
    if (tile >= ntiles) return;
    stage_inputs(sAct0, y, h, tile * SAMP, tid);

    for (; tile < ntiles; tile += gridDim.x) {
        const int srow0 = tile * SAMP;
        __syncthreads();                  // bar1: buf0 inputs ready

        // ---------------- layer 1 (reads buf0) ----------------
        float accP[6][4], accT[6][4];
#pragma unroll
        for (int j = 0; j < 6; j++)
#pragma unroll
            for (int q = 0; q < 4; q++) accP[j][q] = 0.f;

        uint32_t aT[4];
        {
            const float* eb = eps + (size_t)(srow0 + mh * 16) * Dd;
            const int rr = lane >> 2, cc = 2 * (lane & 3);
            aT[0] = packh2(eb[rr * Dd + cc],           eb[rr * Dd + cc + 1]);
            aT[1] = packh2(eb[(rr + 8) * Dd + cc],     eb[(rr + 8) * Dd + cc + 1]);
            aT[2] = packh2(eb[rr * Dd + cc + 8],       eb[rr * Dd + cc + 9]);
            aT[3] = packh2(eb[(rr + 8) * Dd + cc + 8], eb[(rr + 8) * Dd + cc + 9]);
        }

#pragma unroll
        for (int kt = 0; kt < 9; kt++) {
            uint32_t aP[4];
            ldsm4(aP, aAddr(swA0, mh * 16, kt, lane));
#pragma unroll
            for (int np = 0; np < 3; np++) {
                uint32_t b[4];
                ldgB(b, g_w1f, (nq * 3 + np) * 9 + kt, lane);
                mma16816(accP[2 * np],     aP, b[0], b[1]);
                mma16816(accP[2 * np + 1], aP, b[2], b[3]);
            }
        }
        // tangent pass: kt0 only (eps zero beyond k<16)
#pragma unroll
        for (int j = 0; j < 6; j++)
#pragma unroll
            for (int q = 0; q < 4; q++) accT[j][q] = 0.f;
#pragma unroll
        for (int np = 0; np < 3; np++) {
            uint32_t b[4];
            ldgB(b, g_w1f, (nq * 3 + np) * 9 + 0, lane);
            mma16816(accT[2 * np],     aT, b[0], b[1]);
            mma16816(accT[2 * np + 1], aT, b[2], b[3]);
        }

        epilogue(accP, accT, g_b1p, sAct1, mh, n0, lane);
        __syncthreads();                  // bar2: buf1 acts ready; buf0 free

        // ---- prefetch next tile's inputs into buf0 (hides under layer 2) ----
        const int nx = tile + gridDim.x;
        if (nx < ntiles) stage_inputs(sAct0, y, h, nx * SAMP, tid);

        // ---------------- layer 2 (reads buf1) ----------------
#pragma unroll
        for (int j = 0; j < 6; j++)
#pragma unroll
            for (int q = 0; q < 4; q++) { accP[j][q] = 0.f; accT[j][q] = 0.f; }
#pragma unroll
        for (int kt = 0; kt < 12; kt++) {
            uint32_t aP[4], aTk[4];
            ldsm4(aP,  aAddr(swA1, mh * 16,      kt, lane));
            ldsm4(aTk, aAddr(swA1, 32 + mh * 16, kt, lane));
#pragma unroll
            for (int np = 0; np < 3; np++) {
                uint32_t b[4];
                ldgB(b, g_w2f, (nq * 3 + np) * 12 + kt, lane);
                mma16816(accP[2 * np],     aP,  b[0], b[1]);
                mma16816(accP[2 * np + 1], aP,  b[2], b[3]);
                mma16816(accT[2 * np],     aTk, b[0], b[1]);
                mma16816(accT[2 * np + 1], aTk, b[2], b[3]);
            }
        }

        // ---- fused epilogue-2 + layer 3, all in registers ----
        float acc3P[2][4], acc3T[2][4];
#pragma unroll
        for (int j = 0; j < 2; j++)
#pragma unroll
            for (int q = 0; q < 4; q++) { acc3P[j][q] = 0.f; acc3T[j][q] = 0.f; }
        {
            const int cl = 2 * (lane & 3);
#pragma unroll
            for (int ktp = 0; ktp < 3; ktp++) {
                uint32_t aZ[4], aU[4];
#pragma unroll
                for (int hf = 0; hf < 2; hf++) {
                    const int nt = 2 * ktp + hf;
                    const float2 bb = __ldg((const float2*)(b2 + n0 + 8 * nt + cl));
                    float a0 = accP[nt][0] + bb.x, a1 = accP[nt][1] + bb.y;
                    float a2 = accP[nt][2] + bb.x, a3 = accP[nt][3] + bb.y;
                    float g0, g1, p0, p1, g2, g3, p2, p3;
                    gelu2(a0, a1, g0, g1, p0, p1);
                    gelu2(a2, a3, g2, g3, p2, p3);
                    aZ[2 * hf]     = packh2(g0, g1);
                    aZ[2 * hf + 1] = packh2(g2, g3);
                    aU[2 * hf]     = packh2(accT[nt][0] * p0, accT[nt][1] * p1);
                    aU[2 * hf + 1] = packh2(accT[nt][2] * p2, accT[nt][3] * p3);
                }
                uint32_t b[4];
                ldgB(b, g_w3f, nq * 3 + ktp, lane);
                mma16816(acc3P[0], aZ, b[0], b[1]);
                mma16816(acc3P[1], aZ, b[2], b[3]);
                mma16816(acc3T[0], aU, b[0], b[1]);
                mma16816(acc3T[1], aU, b[2], b[3]);
            }
        }
        __syncthreads();                  // bar3: all buf1 L2 reads done

        {   // partials -> sRed (buf1): [nq][64 rows][16]
            float* red = sRed + nq * 1024;
            const int rbase = mh * 16 + (lane >> 2);
            const int cl = 2 * (lane & 3);
#pragma unroll
            for (int nt = 0; nt < 2; nt++)
#pragma unroll
                for (int rh = 0; rh < 2; rh++) {
                    const int r = rbase + 8 * rh;
                    const int c = 8 * nt + cl;
                    *(float2*)(red + r * 16 + c) =
                        make_float2(acc3P[nt][2 * rh], acc3P[nt][2 * rh + 1]);
                    *(float2*)(red + (32 + r) * 16 + c) =
                        make_float2(acc3T[nt][2 * rh], acc3T[nt][2 * rh + 1]);
                }
        }
        __syncthreads();                  // bar4: partials ready

        // ---------------- outputs for this tile ----------------
        {   // zero dh
            float4* dhp = (float4*)(outDh + (size_t)srow0 * CTXd);
            const float4 z4 = make_float4(0.f, 0.f, 0.f, 0.f);
            for (int i = tid; i < 32 * CTXd / 4; i += 256) dhp[i] = z4;
        }
        for (int i = tid; i < 32 * 16; i += 256) {
            const int s = i >> 4, c = i & 15;
            float v = sRed[s * 16 + c] + sRed[1024 + s * 16 + c]
                    + sRed[2048 + s * 16 + c] + sRed[3072 + s * 16 + c];
            outF[(size_t)(srow0 + s) * Dd + c] = v + b3c;
        }
        {
            const int s = tid >> 3, g8 = tid & 7, c0 = 2 * g8;
            const float* rt_ = sRed + 512 + s * 16 + c0;
            float j0 = rt_[0] + rt_[1024] + rt_[2048] + rt_[3072];
            float j1 = rt_[1] + rt_[1025] + rt_[2049] + rt_[3073];
            float2 ev = *(const float2*)(eps + (size_t)(srow0 + s) * Dd + c0);
            float dot = j0 * ev.x + j1 * ev.y;
            dot += __shfl_xor_sync(0xffffffffu, dot, 1);
            dot += __shfl_xor_sync(0xffffffffu, dot, 2);
            dot += __shfl_xor_sync(0xffffffffu, dot, 4);
            if (g8 == 0) outLogp[srow0 + s] = -dot;
        }
    }
}

// ---------------- launcher ----------------
extern "C" void kernel_launch(void* const* d_in, const int* in_sizes, int n_in,
                              void* d_out, int out_size)
{
    const float* t   = (const float*)d_in[0];
    const float* y   = (const float*)d_in[1];
    const float* h   = (const float*)d_in[3];
    const float* eps = (const float*)d_in[4];
    const float* W1  = (const float*)d_in[5];
    const float* b1  = (const float*)d_in[6];
    const float* W2  = (const float*)d_in[7];
    const float* b2  = (const float*)d_in[8];
    const float* W3  = (const float*)d_in[9];
    const float* b3  = (const float*)d_in[10];

    const int Bsz = in_sizes[1] / Dd;
    const int ntiles = Bsz / SAMP;

    const int prepN = (W1BLK + W2BLK + W3BLK) * 128 + 192;
    prep<<<(prepN + 255) / 256, 256>>>(W1, W2, W3, b1, t);

    int smCount = 0;
    cudaDeviceGetAttribute(&smCount, cudaDevAttrMultiProcessorCount, 0);
    if (smCount <= 0) smCount = 148;
    int grid = 3 * smCount;
    if (grid > ntiles) grid = ntiles;

    cudaFuncSetAttribute(odefunc_mma14,
                         cudaFuncAttributeMaxDynamicSharedMemorySize, SM_TOT);
    odefunc_mma14<<<grid, THREADS, SM_TOT>>>(
        y, h, eps, b2, b3, (float*)d_out, Bsz, ntiles);
}